// round 16
// baseline (speedup 1.0000x reference)
#include <cuda_runtime.h>
#include <cstdint>

#define NNODES 16383
#define EMBED 512
#define E4 128          // float4 per H row
#define LEAVES 8192
#define MAXM 4096

// ---------------- device scratch (static, no runtime alloc) ----------------
__device__ float4 g_H[NNODES * E4];          // 33.5 MB hidden states
__device__ float4 g_part[16 * 4096 * 32];    // split-K partials (indexed z*cnt*E4)
__device__ unsigned g_arrive;
__device__ volatile unsigned g_release;

// ---------------- closed-form post-order schedule ----------------
// j-th node of depth d (sub = 2^(d+1)-1 = subtree size):
//   idx = j*sub + (j - popc(j)) + sub - 1
__device__ __forceinline__ int po_idx(int sub, int j) {
    return j * sub + (j - __popc(j)) + sub - 1;
}

// ---------------- f32x2 helpers ----------------
__device__ __forceinline__ void fma2(unsigned long long& d,
                                     unsigned long long a, unsigned long long b) {
    asm("fma.rn.f32x2 %0, %1, %2, %0;" : "+l"(d) : "l"(a), "l"(b));
}
__device__ __forceinline__ unsigned long long pk2(float x, float y) {
    unsigned long long r;
    asm("mov.b64 %0, {%1, %2};" : "=l"(r) : "f"(x), "f"(y));
    return r;
}
__device__ __forceinline__ float2 upk2(unsigned long long v) {
    float2 r;
    asm("mov.b64 {%0, %1}, %2;" : "=f"(r.x), "=f"(r.y) : "l"(v));
    return r;
}

// ---------------- leaves: H[leaf_j] = relu(emb[word[leaf_j]]) --------------
__global__ void k_leaf(const int* __restrict__ word,
                       const float4* __restrict__ emb4) {
    int t = blockIdx.x * blockDim.x + threadIdx.x;
    if (t == 0) { g_arrive = 0; g_release = 0; }     // reset tail barrier
    int j = t >> 7;
    if (j >= LEAVES) return;
    int col = t & 127;
    int node = 2 * j - __popc(j);                    // po_idx(1, j)
    float4 v = emb4[word[node] * E4 + col];
    v.x = fmaxf(v.x, 0.f); v.y = fmaxf(v.y, 0.f);
    v.z = fmaxf(v.z, 0.f); v.w = fmaxf(v.w, 0.f);
    g_H[node * E4 + col] = v;
}

// ---------------- split-K GEMM partial ----------------
// BM=128, BN=128, BK=16, 256 threads, 8x8 micro-tile, f32x2 FMAs.
// Conflict-free read mapping + double-buffered smem (one barrier per chunk).
#define STAGE_F (16 * 132)

__global__ __launch_bounds__(256, 2) void k_partial(
    int ZS, int cnt, int sub,
    const int* __restrict__ left, const int* __restrict__ right,
    const float4* __restrict__ W4)
{
    int z  = blockIdx.z;
    int n0 = blockIdx.y << 7;           // output-col tile base (0..384)
    int kchunk4 = 256 / ZS;             // float4s per K chunk (64/32/16)
    int aoff4 = (z & ((ZS >> 1) - 1)) * kchunk4;   // within-child col (f4)
    int woff4 = z * kchunk4;                        // within-W col (f4)
    bool useRight = (z >= (ZS >> 1));

    __shared__ float As[2][STAGE_F];
    __shared__ float Bs[2][STAGE_F];
    __shared__ int s_src[128];

    int tid = threadIdx.x;
    int lane = tid & 31, w = tid >> 5;
    int wm = w & 3, wn = w >> 2;        // warp grid 4(m) x 2(n)
    int m_lane = lane & 3, n_lane = lane >> 2;
    int am0 = wm * 32 + m_lane * 4;     // A frag base (+0..3, +16)
    int bn0 = wn * 64 + n_lane * 4;     // B frag base (+0..3, +32)

    int c4  = tid & 3;                  // k-f4 chunk within BK tile (store side)
    int row = tid >> 2;                 // 0..63 (row index for loading)

    int bm = blockIdx.x;
    {
        if (tid < 128) {
            int m = bm * 128 + tid;
            int src = 0;
            if (m < cnt) {
                int node = po_idx(sub, m);
                src = useRight ? right[node] : left[node];
            }
            s_src[tid] = src;
        }
        __syncthreads();

        unsigned long long acc[8][4];
#pragma unroll
        for (int i = 0; i < 8; i++)
#pragma unroll
            for (int j = 0; j < 4; j++) acc[i][j] = 0ull;

        // prologue: LDG chunk 0, STS into stage 0, one sync
        float4 va[2], vb[2];
#pragma unroll
        for (int r = 0; r < 2; r++) {
            int mr = row + r * 64;
            va[r] = g_H[s_src[mr] * E4 + aoff4 + c4];
            vb[r] = W4[(n0 + mr) * 256 + woff4 + c4];
        }
#pragma unroll
        for (int r = 0; r < 2; r++) {
            int mr = row + r * 64;
            As[0][(c4 * 4 + 0) * 132 + mr] = va[r].x;
            As[0][(c4 * 4 + 1) * 132 + mr] = va[r].y;
            As[0][(c4 * 4 + 2) * 132 + mr] = va[r].z;
            As[0][(c4 * 4 + 3) * 132 + mr] = va[r].w;
            Bs[0][(c4 * 4 + 0) * 132 + mr] = vb[r].x;
            Bs[0][(c4 * 4 + 1) * 132 + mr] = vb[r].y;
            Bs[0][(c4 * 4 + 2) * 132 + mr] = vb[r].z;
            Bs[0][(c4 * 4 + 3) * 132 + mr] = vb[r].w;
        }
        __syncthreads();

        int nk = kchunk4 >> 2;          // BK16 chunks (16/8/4)
#pragma unroll 1
        for (int it = 0; it < nk; it++) {
            int cur = it & 1, nxt = cur ^ 1;
            bool more = (it + 1 < nk);
            if (more) {
                int k4 = (it + 1) * 4;
#pragma unroll
                for (int r = 0; r < 2; r++) {
                    int mr = row + r * 64;
                    va[r] = g_H[s_src[mr] * E4 + aoff4 + k4 + c4];
                    vb[r] = W4[(n0 + mr) * 256 + woff4 + k4 + c4];
                }
            }

#pragma unroll
            for (int kk = 0; kk < 16; kk++) {
                float4 a0 = *(const float4*)&As[cur][kk * 132 + am0];
                float4 a1 = *(const float4*)&As[cur][kk * 132 + am0 + 16];
                ulonglong2 bq0 = *(const ulonglong2*)&Bs[cur][kk * 132 + bn0];
                ulonglong2 bq1 = *(const ulonglong2*)&Bs[cur][kk * 132 + bn0 + 32];
                unsigned long long b[4] = {bq0.x, bq0.y, bq1.x, bq1.y};
                float a[8] = {a0.x, a0.y, a0.z, a0.w, a1.x, a1.y, a1.z, a1.w};
#pragma unroll
                for (int i = 0; i < 8; i++) {
                    unsigned long long ap = pk2(a[i], a[i]);
                    fma2(acc[i][0], ap, b[0]);
                    fma2(acc[i][1], ap, b[1]);
                    fma2(acc[i][2], ap, b[2]);
                    fma2(acc[i][3], ap, b[3]);
                }
            }

            if (more) {
#pragma unroll
                for (int r = 0; r < 2; r++) {
                    int mr = row + r * 64;
                    As[nxt][(c4 * 4 + 0) * 132 + mr] = va[r].x;
                    As[nxt][(c4 * 4 + 1) * 132 + mr] = va[r].y;
                    As[nxt][(c4 * 4 + 2) * 132 + mr] = va[r].z;
                    As[nxt][(c4 * 4 + 3) * 132 + mr] = va[r].w;
                    Bs[nxt][(c4 * 4 + 0) * 132 + mr] = vb[r].x;
                    Bs[nxt][(c4 * 4 + 1) * 132 + mr] = vb[r].y;
                    Bs[nxt][(c4 * 4 + 2) * 132 + mr] = vb[r].z;
                    Bs[nxt][(c4 * 4 + 3) * 132 + mr] = vb[r].w;
                }
            }
            __syncthreads();            // one barrier per chunk
        }

        float4* pout = g_part + (size_t)z * cnt * E4;
#pragma unroll
        for (int i = 0; i < 8; i++) {
            int lm = am0 + (i & 3) + ((i >> 2) << 4);   // local m row
            int m = bm * 128 + lm;
            if (m < cnt) {
                float2 p0 = upk2(acc[i][0]);
                float2 p1 = upk2(acc[i][1]);
                float2 p2 = upk2(acc[i][2]);
                float2 p3 = upk2(acc[i][3]);
                pout[m * E4 + (n0 >> 2) + (bn0 >> 2)    ] = make_float4(p0.x, p0.y, p1.x, p1.y);
                pout[m * E4 + (n0 >> 2) + (bn0 >> 2) + 8] = make_float4(p2.x, p2.y, p3.x, p3.y);
            }
        }
    }
}

// ---------------- combine partials + bias + relu -> H ----------------
__global__ void k_combine(int ZS, int cnt, int sub,
                          const float4* __restrict__ bW4) {
    int total = cnt * E4;
    for (int idx = blockIdx.x * blockDim.x + threadIdx.x; idx < total;
         idx += gridDim.x * blockDim.x) {
        int m = idx >> 7, j = idx & 127;
        float4 s = g_part[m * E4 + j];
        for (int z = 1; z < ZS; z++) {
            float4 p = g_part[((size_t)z * cnt + m) * E4 + j];
            s.x += p.x; s.y += p.y; s.z += p.z; s.w += p.w;
        }
        float4 b = bW4[j];
        s.x = fmaxf(s.x + b.x, 0.f);
        s.y = fmaxf(s.y + b.y, 0.f);
        s.z = fmaxf(s.z + b.z, 0.f);
        s.w = fmaxf(s.w + b.w, 0.f);
        g_H[po_idx(sub, m) * E4 + j] = s;
    }
}

// ---------------- fused deep tail: levels 8..13 in ONE kernel ------------
// grid = (32, 4) = 128 blocks (co-resident on 148 SMs); sense-reversing
// grid barrier between levels. Counters reset by k_leaf every launch.
__device__ __forceinline__ void gbar(unsigned nb, unsigned& phase) {
    __threadfence();
    __syncthreads();
    if (threadIdx.x == 0) {
        unsigned t = atomicAdd(&g_arrive, 1u);
        if (t == phase * nb + (nb - 1)) {
            g_release = phase + 1;
        } else {
            while (g_release <= phase) { }
        }
        __threadfence();
    }
    __syncthreads();
    phase++;
}

__global__ __launch_bounds__(256) void k_tail(
    const int* __restrict__ left, const int* __restrict__ right,
    const float4* __restrict__ W4, const float* __restrict__ bW)
{
    __shared__ float4 pair[256];   // 1024 floats = [h_l ; h_r]
    int tid = threadIdx.x;
    int lane = tid & 31, w = tid >> 5;
    int n0 = blockIdx.y << 7;
    float* Hf = (float*)g_H;
    unsigned phase = 0;
    const unsigned NB = 32u * 4u;

#pragma unroll 1
    for (int d = 8; d <= 13; d++) {
        int cnt = LEAVES >> d;
        int sub = (2 << d) - 1;
        if ((int)blockIdx.x < cnt) {
            int node = po_idx(sub, blockIdx.x);
            int cl = left[node], cr = right[node];
            pair[tid] = (tid < 128) ? g_H[cl * E4 + tid] : g_H[cr * E4 + tid - 128];
            __syncthreads();
#pragma unroll 1
            for (int o = 0; o < 16; o++) {
                int n = n0 + w * 16 + o;
                const float4* wrow = W4 + n * 256;
                float acc = 0.f;
#pragma unroll
                for (int it = 0; it < 8; it++) {
                    float4 wv = wrow[lane + it * 32];
                    float4 pv = pair[lane + it * 32];
                    acc += wv.x * pv.x + wv.y * pv.y + wv.z * pv.z + wv.w * pv.w;
                }
#pragma unroll
                for (int off = 16; off; off >>= 1)
                    acc += __shfl_xor_sync(0xffffffffu, acc, off);
                if (lane == 0)
                    Hf[node * EMBED + n] = fmaxf(acc + bW[n], 0.f);
            }
            __syncthreads();
        }
        gbar(NB, phase);
    }
}

// ---------------- logits: out[i][c] = H[i] . P[c] + bP[c] ----------------
__global__ void k_logits(const float4* __restrict__ P4,
                         const float* __restrict__ bP,
                         float* __restrict__ out) {
    int gw = (blockIdx.x * blockDim.x + threadIdx.x) >> 5;
    int lane = threadIdx.x & 31;
    if (gw >= NNODES) return;
    float4 h[4];
#pragma unroll
    for (int i = 0; i < 4; i++) h[i] = g_H[gw * E4 + lane + i * 32];
#pragma unroll
    for (int c = 0; c < 5; c++) {
        float acc = 0.f;
#pragma unroll
        for (int i = 0; i < 4; i++) {
            float4 p = P4[c * E4 + lane + i * 32];
            acc += p.x * h[i].x + p.y * h[i].y + p.z * h[i].z + p.w * h[i].w;
        }
#pragma unroll
        for (int off = 16; off; off >>= 1)
            acc += __shfl_xor_sync(0xffffffffu, acc, off);
        if (lane == 0) out[gw * 5 + c] = acc + bP[c];
    }
}

// ---------------- launch ----------------
extern "C" void kernel_launch(void* const* d_in, const int* in_sizes, int n_in,
                              void* d_out, int out_size) {
    const int*   word    = (const int*)d_in[1];
    const int*   left    = (const int*)d_in[2];
    const int*   right   = (const int*)d_in[3];
    const float* emb     = (const float*)d_in[4];
    const float* W       = (const float*)d_in[5];
    const float* bW      = (const float*)d_in[6];
    const float* P       = (const float*)d_in[7];
    const float* bP      = (const float*)d_in[8];
    float* out = (float*)d_out;

    k_leaf<<<(LEAVES * 128 + 255) / 256, 256>>>(word, (const float4*)emb);

    for (int d = 1; d <= 7; d++) {
        int cnt = LEAVES >> d;
        int sub = (2 << d) - 1;
        int ZS = (d <= 3) ? 4 : (d == 4 ? 8 : 16);
        int mt = (cnt + 127) / 128; if (mt < 1) mt = 1;
        k_partial<<<dim3(mt, 4, ZS), 256>>>(ZS, cnt, sub, left, right,
                                            (const float4*)W);
        int cb = (cnt * 128 + 255) / 256; if (cb < 1) cb = 1;
        k_combine<<<cb, 256>>>(ZS, cnt, sub, (const float4*)bW);
    }

    // levels 8..13 fused with grid-wide barrier
    k_tail<<<dim3(32, 4), 256>>>(left, right, (const float4*)W, bW);

    k_logits<<<(NNODES * 32 + 255) / 256, 256>>>((const float4*)P, bP, out);
}